// round 12
// baseline (speedup 1.0000x reference)
#include <cuda_runtime.h>
#include <cuda_fp16.h>
#include <math.h>
#include <stdint.h>

#define D_MODEL 1024
#define D_FF    4096
#define N_EXP   8
#define MAX_N   4096
#define MAX_PAIRS (2*MAX_N)
#define NBLOCKS 296

// ---- scratch (static device globals; no runtime allocation) ----
__device__ __half g_xh[(size_t)MAX_N * D_MODEL];
__device__ __half g_W1t[(size_t)N_EXP * D_FF * D_MODEL];   // [e][n=4096][k=1024]
__device__ __half g_W2t[(size_t)N_EXP * D_MODEL * D_FF];   // [e][n=1024][k=4096]
__device__ __half g_Hh[(size_t)MAX_PAIRS * D_FF];
__device__ float  g_pairout[(size_t)MAX_PAIRS * D_MODEL];
__device__ int    g_pairlist[MAX_PAIRS];
__device__ int    g_cnt[N_EXP];
__device__ int    g_off[N_EXP];
__device__ int    g_tokexp[MAX_PAIRS];
__device__ float  g_tokw[MAX_PAIRS];
__device__ int    g_done1[N_EXP];     // GEMM1 tiles completed per expert

__device__ __forceinline__ float gelu_exact(float v) {
    return 0.5f * v * (1.0f + erff(v * 0.70710678118654752440f));
}
__device__ __forceinline__ uint32_t smem_u32(const void* p) {
    uint32_t a;
    asm("{ .reg .u64 t; cvta.to.shared.u64 t, %1; cvt.u32.u64 %0, t; }" : "=r"(a) : "l"(p));
    return a;
}
__device__ __forceinline__ void cp_async16(uint32_t dst, const void* src, int srcsize) {
    asm volatile("cp.async.ca.shared.global [%0], [%1], 16, %2;"
                 :: "r"(dst), "l"(src), "r"(srcsize) : "memory");
}
__device__ __forceinline__ void cp_commit() { asm volatile("cp.async.commit_group;" ::: "memory"); }
__device__ __forceinline__ void cp_wait1()  { asm volatile("cp.async.wait_group 1;" ::: "memory"); }

__device__ __forceinline__ void ldsm_x4(uint32_t* r, uint32_t addr) {
    asm volatile("ldmatrix.sync.aligned.m8n8.x4.shared.b16 {%0,%1,%2,%3}, [%4];"
                 : "=r"(r[0]), "=r"(r[1]), "=r"(r[2]), "=r"(r[3]) : "r"(addr));
}
__device__ __forceinline__ void mma_f16(float* d, const uint32_t* a, const uint32_t* b) {
    asm volatile(
        "mma.sync.aligned.m16n8k16.row.col.f32.f16.f16.f32 "
        "{%0,%1,%2,%3}, {%4,%5,%6,%7}, {%8,%9}, {%0,%1,%2,%3};"
        : "+f"(d[0]), "+f"(d[1]), "+f"(d[2]), "+f"(d[3])
        : "r"(a[0]), "r"(a[1]), "r"(a[2]), "r"(a[3]), "r"(b[0]), "r"(b[1]));
}

// ---------------- gate ----------------
__global__ void gate_kernel(const float* __restrict__ x,
                            const float* __restrict__ gw, int N) {
    __shared__ float s_gw[N_EXP][D_MODEL];
    int tid = threadIdx.x;
    for (int i = tid; i < N_EXP * D_MODEL / 4; i += blockDim.x) {
        float4 v = ((const float4*)gw)[i];
        int e = i >> 8, c = (i & 255) * 4;
        s_gw[e][c] = v.x; s_gw[e][c + 1] = v.y; s_gw[e][c + 2] = v.z; s_gw[e][c + 3] = v.w;
    }
    __syncthreads();

    int warp = tid >> 5, lane = tid & 31;
    int t = blockIdx.x * 8 + warp;
    if (t >= N) return;

    const float4* xr = (const float4*)(x + (size_t)t * D_MODEL);
    float acc[N_EXP];
#pragma unroll
    for (int e = 0; e < N_EXP; e++) acc[e] = 0.f;
#pragma unroll
    for (int it = 0; it < D_MODEL / 128; it++) {
        int d4 = it * 32 + lane;
        float4 xv = xr[d4];
        int d = d4 * 4;
#pragma unroll
        for (int e = 0; e < N_EXP; e++) {
            acc[e] += xv.x * s_gw[e][d] + xv.y * s_gw[e][d + 1]
                    + xv.z * s_gw[e][d + 2] + xv.w * s_gw[e][d + 3];
        }
    }
#pragma unroll
    for (int e = 0; e < N_EXP; e++) {
#pragma unroll
        for (int o = 16; o > 0; o >>= 1)
            acc[e] += __shfl_xor_sync(0xffffffffu, acc[e], o);
    }
    if (lane == 0) {
        float mx = acc[0];
#pragma unroll
        for (int e = 1; e < N_EXP; e++) mx = fmaxf(mx, acc[e]);
        float p[N_EXP]; float sum = 0.f;
#pragma unroll
        for (int e = 0; e < N_EXP; e++) { p[e] = expf(acc[e] - mx); sum += p[e]; }
        float inv = 1.0f / sum;
#pragma unroll
        for (int e = 0; e < N_EXP; e++) p[e] *= inv;
        int e0 = 0;
#pragma unroll
        for (int e = 1; e < N_EXP; e++) if (p[e] > p[e0]) e0 = e;
        int e1 = (e0 == 0) ? 1 : 0;
#pragma unroll
        for (int e = 0; e < N_EXP; e++) if (e != e0 && p[e] > p[e1]) e1 = e;
        g_tokexp[2 * t + 0] = e0; g_tokw[2 * t + 0] = p[e0];
        g_tokexp[2 * t + 1] = e1; g_tokw[2 * t + 1] = p[e1];
    }
}

// ------- compaction + zero done-counters -------
__global__ void build_kernel(int N) {
    __shared__ int s_cnt[N_EXP];
    int tid = threadIdx.x, warp = tid >> 5, lane = tid & 31;
    int total = 2 * N;
    if (tid < N_EXP) g_done1[tid] = 0;
    if (warp < N_EXP) {
        int c = 0;
        for (int i = lane; i < total; i += 32) c += (g_tokexp[i] == warp);
#pragma unroll
        for (int o = 16; o > 0; o >>= 1) c += __shfl_xor_sync(0xffffffffu, c, o);
        if (lane == 0) s_cnt[warp] = c;
    }
    __syncthreads();
    if (tid == 0) {
        int o = 0;
        for (int e = 0; e < N_EXP; e++) { g_off[e] = o; g_cnt[e] = s_cnt[e]; o += s_cnt[e]; }
    }
    __syncthreads();
    if (warp < N_EXP) {
        int run = g_off[warp];
        for (int base = 0; base < total; base += 32) {
            int i = base + lane;
            bool m = (i < total) && (g_tokexp[i] == warp);
            unsigned b = __ballot_sync(0xffffffffu, m);
            if (m) g_pairlist[run + __popc(b & ((1u << lane) - 1u))] = i;
            run += __popc(b);
        }
    }
}

// ---------------- prepass ----------------
__global__ void convert_x_kernel(const float* __restrict__ x, int total4) {
    int i = blockIdx.x * blockDim.x + threadIdx.x;
    if (i >= total4) return;
    float4 v = ((const float4*)x)[i];
    __half2* o = (__half2*)g_xh;
    o[2 * i + 0] = __floats2half2_rn(v.x, v.y);
    o[2 * i + 1] = __floats2half2_rn(v.z, v.w);
}

__global__ void transpose_kernel(const float* __restrict__ src, __half* __restrict__ dst,
                                 int K, int Nn) {
    __shared__ float tile[32][33];
    int e = blockIdx.z;
    const float* s = src + (size_t)e * K * Nn;
    __half* d = dst + (size_t)e * K * Nn;
    int n0 = blockIdx.x * 32, k0 = blockIdx.y * 32;
    int tx = threadIdx.x, ty = threadIdx.y;
#pragma unroll
    for (int r = 0; r < 32; r += 8)
        tile[ty + r][tx] = s[(size_t)(k0 + ty + r) * Nn + n0 + tx];
    __syncthreads();
    int tid = ty * 32 + tx;
    int row = tid >> 3, ch = tid & 7;
    float v0 = tile[ch * 4 + 0][row];
    float v1 = tile[ch * 4 + 1][row];
    float v2 = tile[ch * 4 + 2][row];
    float v3 = tile[ch * 4 + 3][row];
    __half2 h0 = __floats2half2_rn(v0, v1);
    __half2 h1 = __floats2half2_rn(v2, v3);
    uint2 pack = make_uint2(*(uint32_t*)&h0, *(uint32_t*)&h1);
    *(uint2*)(d + (size_t)(n0 + row) * K + k0 + ch * 4) = pack;
}

// =================== fused persistent GEMM1+GEMM2 ===================
#define PITCH 144
#define A_STAGE_BYTES (128 * PITCH)
#define STAGE_BYTES   (2 * 128 * PITCH)
#define N_STAGES 2
#define SMEM_TOT (2048 + N_STAGES * STAGE_BYTES)

// per-tile GEMM body: 128x128 tile at (e, fn0, row0)
template <int MODE>
__device__ __forceinline__ void run_tile(const __half* __restrict__ Wt,
                                         int e, int fn0, int row0, int cnt, int off,
                                         char* smem, uint32_t stage_base,
                                         int tid, int wid, int lane) {
    constexpr int Ktot = (MODE == 0) ? D_MODEL : D_FF;
    constexpr int ITERS = Ktot / 64;
    const __half** s_aptr = (const __half**)smem;
    int* s_pair = (int*)(smem + 1024);

    __syncthreads();   // protect previous tile's smem use
    if (tid < 128) {
        int r = row0 + tid;
        const __half* ip = nullptr; int p = -1;
        if (r < cnt) {
            p = g_pairlist[off + r];
            ip = (MODE == 0) ? (g_xh + (size_t)(p >> 1) * D_MODEL)
                             : (g_Hh + (size_t)p * D_FF);
        }
        s_aptr[tid] = ip; s_pair[tid] = p;
    }
    __syncthreads();

    int srow = tid >> 1;
    int halfsel = tid & 1;
    const __half* arow = s_aptr[srow];
    int a_sz = arow ? 16 : 0;
    if (!arow) arow = g_xh;
    const __half* We = Wt + (size_t)e * Ktot * ((MODE == 0) ? D_FF : D_MODEL);
    const __half* brow = We + (size_t)(fn0 + srow) * Ktot;

    auto stage = [&](int it) {
        if (it < ITERS) {
            uint32_t sA = stage_base + (it % N_STAGES) * STAGE_BYTES + srow * PITCH + halfsel * 64;
            uint32_t sB = sA + A_STAGE_BYTES;
            const char* ga = (const char*)(arow + it * 64) + halfsel * 64;
            const char* gb = (const char*)(brow + it * 64) + halfsel * 64;
#pragma unroll
            for (int c = 0; c < 4; c++) cp_async16(sA + c * 16, ga + c * 16, a_sz);
#pragma unroll
            for (int c = 0; c < 4; c++) cp_async16(sB + c * 16, gb + c * 16, 16);
        }
        cp_commit();
    };

    float d[4][4][4];
#pragma unroll
    for (int i = 0; i < 4; i++)
#pragma unroll
        for (int j = 0; j < 4; j++)
#pragma unroll
            for (int r = 0; r < 4; r++) d[i][j][r] = 0.f;

    int wm = wid >> 2, wn = wid & 3;
    int a_row_l = (lane & 15);
    int a_koff  = (lane >> 4) * 16;
    int b_grp   = lane >> 3;
    int b_row_l = (b_grp >> 1) * 8 + (lane & 7);
    int b_koff  = (b_grp & 1) * 16;

    stage(0);
    stage(1);

    for (int it = 0; it < ITERS; ++it) {
        cp_wait1();
        __syncthreads();
        uint32_t A = stage_base + (it % N_STAGES) * STAGE_BYTES;
        uint32_t B = A + A_STAGE_BYTES;
#pragma unroll
        for (int ks = 0; ks < 4; ks++) {
            uint32_t a[4][4], b[2][4];
#pragma unroll
            for (int i = 0; i < 4; i++)
                ldsm_x4(a[i], A + (wm * 64 + i * 16 + a_row_l) * PITCH + ks * 32 + a_koff);
#pragma unroll
            for (int jj = 0; jj < 2; jj++)
                ldsm_x4(b[jj], B + (wn * 32 + jj * 16 + b_row_l) * PITCH + ks * 32 + b_koff);
#pragma unroll
            for (int i = 0; i < 4; i++)
#pragma unroll
                for (int j = 0; j < 4; j++)
                    mma_f16(d[i][j], a[i], &b[j >> 1][(j & 1) * 2]);
        }
        __syncthreads();
        stage(it + 2);
    }

    int g = lane >> 2, t4 = lane & 3;
#pragma unroll
    for (int i = 0; i < 4; i++) {
        int rl = wm * 64 + i * 16 + g;
        int pL = s_pair[rl], pH = s_pair[rl + 8];
#pragma unroll
        for (int j = 0; j < 4; j++) {
            int c = wn * 32 + j * 8 + t4 * 2;
            if (MODE == 0) {
                if (pL >= 0) {
                    __half2* o = (__half2*)(g_Hh + (size_t)pL * D_FF + fn0 + c);
                    *o = __floats2half2_rn(gelu_exact(d[i][j][0]), gelu_exact(d[i][j][1]));
                }
                if (pH >= 0) {
                    __half2* o = (__half2*)(g_Hh + (size_t)pH * D_FF + fn0 + c);
                    *o = __floats2half2_rn(gelu_exact(d[i][j][2]), gelu_exact(d[i][j][3]));
                }
            } else {
                if (pL >= 0) {
                    float w = g_tokw[pL];
                    *(float2*)(g_pairout + (size_t)pL * D_MODEL + fn0 + c) =
                        make_float2(w * d[i][j][0], w * d[i][j][1]);
                }
                if (pH >= 0) {
                    float w = g_tokw[pH];
                    *(float2*)(g_pairout + (size_t)pH * D_MODEL + fn0 + c) =
                        make_float2(w * d[i][j][2], w * d[i][j][3]);
                }
            }
        }
    }
}

__global__ void __launch_bounds__(256, 2) moe_fused(const __half* __restrict__ W1t,
                                                    const __half* __restrict__ W2t) {
    extern __shared__ __align__(128) char smem[];
    // sched block at [1536, 2048): rt[8], c1[9], c2[9], cnt[8], off[8]
    int* s_rt  = (int*)(smem + 1536);
    int* s_c1  = s_rt + 8;    // 9 ints
    int* s_c2  = s_c1 + 9;    // 9 ints
    int* s_cn  = s_c2 + 9;    // 8 ints
    int* s_of  = s_cn + 8;    // 8 ints
    uint32_t stage_base = smem_u32(smem) + 2048;

    int tid = threadIdx.x, wid = tid >> 5, lane = tid & 31;

    if (tid == 0) {
        int a1 = 0, a2 = 0;
        for (int e = 0; e < N_EXP; e++) {
            int cnt = g_cnt[e];
            int rt = (cnt + 127) >> 7;
            s_rt[e] = rt; s_cn[e] = cnt; s_of[e] = g_off[e];
            s_c1[e] = a1; a1 += 32 * rt;
            s_c2[e] = a2; a2 += 8 * rt;
        }
        s_c1[N_EXP] = a1; s_c2[N_EXP] = a2;
    }
    __syncthreads();
    int total1 = s_c1[N_EXP];
    int total  = total1 + s_c2[N_EXP];

    for (int idx = blockIdx.x; idx < total; idx += gridDim.x) {
        if (idx < total1) {
            int e = N_EXP - 1;
            for (int k = 0; k < N_EXP - 1; k++) if (idx < s_c1[k + 1]) { e = k; break; }
            int local = idx - s_c1[e];
            int fn0  = (local & 31) * 128;
            int row0 = (local >> 5) * 128;
            run_tile<0>(W1t, e, fn0, row0, s_cn[e], s_of[e], smem, stage_base, tid, wid, lane);
            // release: make H visible, then count the tile
            __threadfence();
            __syncthreads();
            if (tid == 0) atomicAdd(&g_done1[e], 1);
        } else {
            int j = idx - total1;
            int e = N_EXP - 1;
            for (int k = 0; k < N_EXP - 1; k++) if (j < s_c2[k + 1]) { e = k; break; }
            int local = j - s_c2[e];
            int fn0  = (local & 7) * 128;
            int row0 = (local >> 3) * 128;
            // acquire: expert e's GEMM1 fully done
            if (tid == 0) {
                int target = 32 * s_rt[e];
                while (atomicAdd(&g_done1[e], 0) < target) __nanosleep(200);
                __threadfence();
            }
            __syncthreads();
            run_tile<1>(W2t, e, fn0, row0, s_cn[e], s_of[e], smem, stage_base, tid, wid, lane);
        }
    }
}

// ---------------- combine ----------------
__global__ void combine_kernel(float* __restrict__ out, int N) {
    int idx = blockIdx.x * blockDim.x + threadIdx.x;
    int total = N * (D_MODEL / 4);
    if (idx >= total) return;
    int t = idx / (D_MODEL / 4);
    int d4 = idx - t * (D_MODEL / 4);
    const float4* po = (const float4*)g_pairout;
    float4 a = po[(size_t)(2 * t) * (D_MODEL / 4) + d4];
    float4 b = po[(size_t)(2 * t + 1) * (D_MODEL / 4) + d4];
    ((float4*)out)[idx] = make_float4(a.x + b.x, a.y + b.y, a.z + b.z, a.w + b.w);
}

extern "C" void kernel_launch(void* const* d_in, const int* in_sizes, int n_in,
                              void* d_out, int out_size) {
    const float* x  = (const float*)d_in[0];
    const float* gw = (const float*)d_in[1];
    const float* W1 = (const float*)d_in[2];
    const float* W2 = (const float*)d_in[3];
    int N = in_sizes[0] / D_MODEL;

    static cudaStream_t s1, s2, s3;
    static cudaEvent_t ev_root, ev_s1, ev_s2, ev_s3;
    static __half *w1t, *w2t;
    static bool init_done = false;
    if (!init_done) {
        cudaFuncSetAttribute(moe_fused, cudaFuncAttributeMaxDynamicSharedMemorySize, SMEM_TOT);
        cudaStreamCreateWithFlags(&s1, cudaStreamNonBlocking);
        cudaStreamCreateWithFlags(&s2, cudaStreamNonBlocking);
        cudaStreamCreateWithFlags(&s3, cudaStreamNonBlocking);
        cudaEventCreateWithFlags(&ev_root, cudaEventDisableTiming);
        cudaEventCreateWithFlags(&ev_s1, cudaEventDisableTiming);
        cudaEventCreateWithFlags(&ev_s2, cudaEventDisableTiming);
        cudaEventCreateWithFlags(&ev_s3, cudaEventDisableTiming);
        cudaGetSymbolAddress((void**)&w1t, g_W1t);
        cudaGetSymbolAddress((void**)&w2t, g_W2t);
        init_done = true;
    }

    dim3 blkT(32, 8);
    dim3 gt1(D_FF / 32, D_MODEL / 32, N_EXP);
    dim3 gt2(D_MODEL / 32, D_FF / 32, N_EXP);

    // fork prepass
    cudaEventRecord(ev_root, 0);
    cudaStreamWaitEvent(s1, ev_root, 0);
    cudaStreamWaitEvent(s2, ev_root, 0);
    cudaStreamWaitEvent(s3, ev_root, 0);

    convert_x_kernel<<<(N * D_MODEL / 4 + 255) / 256, 256, 0, s1>>>(x, N * D_MODEL / 4);
    cudaEventRecord(ev_s1, s1);

    transpose_kernel<<<gt1, blkT, 0, s2>>>(W1, w1t, D_MODEL, D_FF);
    cudaEventRecord(ev_s2, s2);

    transpose_kernel<<<gt2, blkT, 0, s3>>>(W2, w2t, D_FF, D_MODEL);
    cudaEventRecord(ev_s3, s3);

    // main: gate + build (also zeroes done counters)
    gate_kernel<<<(N + 7) / 8, 256>>>(x, gw, N);
    build_kernel<<<1, 256>>>(N);

    // fused GEMM needs everything
    cudaStreamWaitEvent(0, ev_s1, 0);
    cudaStreamWaitEvent(0, ev_s2, 0);
    cudaStreamWaitEvent(0, ev_s3, 0);
    moe_fused<<<NBLOCKS, 256, SMEM_TOT>>>(w1t, w2t);

    combine_kernel<<<(N * (D_MODEL / 4) + 255) / 256, 256>>>((float*)d_out, N);
}